// round 14
// baseline (speedup 1.0000x reference)
#include <cuda_runtime.h>
#include <cstdint>

// Problem constants (from reference)
#define NROW0 50
#define NROW1 50
#define NROW2 50
#define NPAIR (NROW0 * NROW1)       // 2500 (d0,d1) combos
#define TROW  512                   // t row = 16 (k) x 32 (r2) floats
#define G1LEN 4096                  // core1 row: 32*4*32
#define G0LEN 128                   // core0 row: 1*4*32
#define G2LEN 256                   // core2 row: 32*8
#define EMBD  128

// Scratch (global, allocation-free)
__device__ __align__(16) float g_t_table[NPAIR * TROW];   // [p][k*32+r], 5.12 MB (L2)
__device__ __align__(16) float g_core2t[NROW2 * G2LEN];   // [d2][z*32+r], 51.2 KB (L1)

// ---------------------------------------------------------------------------
// Stage 1 (fused): blocks 0..2499 build t_table; blocks 2500..2549 transpose
// core2 into [d2][z*32+r].  (2 launches keeps ncu -s 5 on bag_kernel.)
// ---------------------------------------------------------------------------
__global__ void __launch_bounds__(128) tt_stage1(const float* __restrict__ core0,
                                                 const float* __restrict__ core1,
                                                 const float* __restrict__ core2)
{
    const int tid = threadIdx.x;

    if (blockIdx.x >= NPAIR) {
        const int base = (blockIdx.x - NPAIR) * G2LEN;
        #pragma unroll
        for (int h = 0; h < 2; ++h) {
            const int u   = base + h * 128 + tid;
            const int d2  = u >> 8;
            const int rem = u & 255;
            const int r   = rem >> 3;
            const int z   = rem & 7;
            g_core2t[(d2 << 8) + (z << 5) + r] = core2[u];
        }
        return;
    }

    __shared__ __align__(16) float s_g1[G1LEN];
    __shared__ __align__(16) float s_g0[G0LEN];
    const int p  = blockIdx.x;
    const int d0 = p / NROW1;
    const int d1 = p - d0 * NROW1;

    const float4* __restrict__ g1v = (const float4*)(core1 + (size_t)d1 * G1LEN);
    float4* s1v = (float4*)s_g1;
    #pragma unroll
    for (int t = 0; t < G1LEN / 4 / 128; ++t)
        s1v[t * 128 + tid] = __ldg(g1v + t * 128 + tid);
    if (tid < G0LEN / 4)
        ((float4*)s_g0)[tid] = __ldg((const float4*)(core0 + d0 * G0LEN) + tid);
    __syncthreads();

    float a0 = 0.f, a1 = 0.f, a2 = 0.f, a3 = 0.f;
    #pragma unroll
    for (int r = 0; r < 32; ++r) {
        const float v = s_g1[r * 128 + tid];
        a0 = fmaf(s_g0[r],      v, a0);
        a1 = fmaf(s_g0[32 + r], v, a1);
        a2 = fmaf(s_g0[64 + r], v, a2);
        a3 = fmaf(s_g0[96 + r], v, a3);
    }
    float* o = g_t_table + (size_t)p * TROW;
    o[tid]       = a0;
    o[tid + 128] = a1;
    o[tid + 256] = a2;
    o[tid + 384] = a3;
}

// ---------------------------------------------------------------------------
// Stage 2: one bag per block; each TT index handled by ONE warp (4-way split).
// Lane (q=lane>>3, c8=lane&7): 4x8 scalar register tile acc[m][z]  (R12).
// TT pipeline: idx prefetched 2 iterations ahead, t row 1 ahead.
// FUSED cache gather: each TT iteration also issues one independent cache-row
// LDG.128 (+next-y prefetch), hiding cache L2 latency under the FMA block.
// Leftover cache rows drain in a short tail loop.
// ---------------------------------------------------------------------------
__global__ void __launch_bounds__(128, 5) bag_kernel(
    const int*   __restrict__ indices,
    const int*   __restrict__ offsets,
    const int*   __restrict__ cached_indices,
    const int*   __restrict__ cached_offsets,
    const float* __restrict__ cache_table,
    float*       __restrict__ out,
    int num_bags,
    int n_cached)
{
    __shared__ float s_part[4][EMBD];
    __shared__ __align__(16) float s_cache[4][EMBD];
    const int tid  = threadIdx.x;
    const int w    = tid >> 5;
    const int lane = tid & 31;
    const int q    = lane >> 3;
    const int c8   = lane & 7;
    const int b    = blockIdx.x;

    const int i0 = __ldg(offsets + b);
    const int i1 = __ldg(offsets + b + 1);
    const int j0 = __ldg(cached_offsets + b);
    const int j1 = __ldg(cached_offsets + b + 1);
    const int jlast = j1 - 1;
    const int jcap  = n_cached - 1;

    float acc[4][8];
    #pragma unroll
    for (int m = 0; m < 4; ++m)
        #pragma unroll
        for (int z = 0; z < 8; ++z) acc[m][z] = 0.f;

    float4 cv = make_float4(0.f, 0.f, 0.f, 0.f);
    int j = j0 + w;                       // cache cursor for this warp
    int y_c = 0;                          // current cached row id (clamped-safe)
    {
        const int js = (j <= jlast) ? j : (j0 < n_cached ? j0 : 0);
        y_c = __ldg(cached_indices + (js <= jcap ? js : jcap));
    }

    // ---- TT bag (pipelined) fused with cache-row gather ----
    {
        const float4* __restrict__ tbase = (const float4*)g_t_table;
        const int toff = q * 32 + c8;
        const int ilast = i1 - 1;

        int i = i0 + w;
        int d2_c = 0;
        int idx_n = 0;
        float4 t0, t1, t2, t3;

        if (i < i1) {
            const int idx = __ldg(indices + i);
            const int pq  = idx / 50;
            d2_c = idx - pq * 50;
            const float4* tr = tbase + pq * 128 + toff;
            t0 = __ldcg(tr);
            t1 = __ldcg(tr + 8);
            t2 = __ldcg(tr + 16);
            t3 = __ldcg(tr + 24);
            const int in4 = (i + 4 <= ilast) ? (i + 4) : i;
            idx_n = __ldg(indices + in4);
        }

        #pragma unroll 2
        for (; i < i1; i += 4) {
            // TT stage 0: idx for i+8.
            const int in8 = (i + 8 <= ilast) ? (i + 8) : i;
            const int idx_nn = __ldg(indices + in8);

            // Cache: issue row load for current y_c (independent of TT chain),
            // prefetch next cached index (clamped).
            const bool jv = (j <= jlast);
            const float4 cf = __ldcg(
                (const float4*)(cache_table + (size_t)y_c * EMBD) + lane);
            const int jn  = (j + 4 <= jlast) ? (j + 4) : j;
            const int y_n = __ldg(cached_indices + (jn <= jcap ? jn : jcap));

            // TT stage 1: idx_n -> div -> t loads for i+4.
            const int pq_n = idx_n / 50;
            const int d2_n = idx_n - pq_n * 50;
            const float4* trn = tbase + pq_n * 128 + toff;
            const float4 n0 = __ldcg(trn);
            const float4 n1 = __ldcg(trn + 8);
            const float4 n2 = __ldcg(trn + 16);
            const float4 n3 = __ldcg(trn + 24);

            // TT stage 2: FMA block for current index i.
            const float4* __restrict__ cr =
                (const float4*)g_core2t + (d2_c << 6) + c8;

            #define FMA_Z(CZ, Z)                                       \
                acc[0][Z] = fmaf(t0.x, CZ.x, acc[0][Z]);               \
                acc[0][Z] = fmaf(t0.y, CZ.y, acc[0][Z]);               \
                acc[0][Z] = fmaf(t0.z, CZ.z, acc[0][Z]);               \
                acc[0][Z] = fmaf(t0.w, CZ.w, acc[0][Z]);               \
                acc[1][Z] = fmaf(t1.x, CZ.x, acc[1][Z]);               \
                acc[1][Z] = fmaf(t1.y, CZ.y, acc[1][Z]);               \
                acc[1][Z] = fmaf(t1.z, CZ.z, acc[1][Z]);               \
                acc[1][Z] = fmaf(t1.w, CZ.w, acc[1][Z]);               \
                acc[2][Z] = fmaf(t2.x, CZ.x, acc[2][Z]);               \
                acc[2][Z] = fmaf(t2.y, CZ.y, acc[2][Z]);               \
                acc[2][Z] = fmaf(t2.z, CZ.z, acc[2][Z]);               \
                acc[2][Z] = fmaf(t2.w, CZ.w, acc[2][Z]);               \
                acc[3][Z] = fmaf(t3.x, CZ.x, acc[3][Z]);               \
                acc[3][Z] = fmaf(t3.y, CZ.y, acc[3][Z]);               \
                acc[3][Z] = fmaf(t3.z, CZ.z, acc[3][Z]);               \
                acc[3][Z] = fmaf(t3.w, CZ.w, acc[3][Z]);

            {
                float4 c0 = __ldg(cr);
                float4 c1 = __ldg(cr + 8);
                float4 c2 = __ldg(cr + 16);
                float4 c3 = __ldg(cr + 24);
                FMA_Z(c0, 0) FMA_Z(c1, 1) FMA_Z(c2, 2) FMA_Z(c3, 3)
            }
            {
                float4 c4 = __ldg(cr + 32);
                float4 c5 = __ldg(cr + 40);
                float4 c6 = __ldg(cr + 48);
                float4 c7 = __ldg(cr + 56);
                FMA_Z(c4, 4) FMA_Z(c5, 5) FMA_Z(c6, 6) FMA_Z(c7, 7)
            }
            #undef FMA_Z

            // Cache accumulate (predicated) + advance.
            if (jv) {
                cv.x += cf.x; cv.y += cf.y; cv.z += cf.z; cv.w += cf.w;
                j = j + 4;
            }
            y_c = y_n;

            // Rotate TT pipeline (renamed away by unroll-2).
            t0 = n0; t1 = n1; t2 = n2; t3 = n3;
            d2_c = d2_n;
            idx_n = idx_nn;
        }
    }

    // ---- cache tail (cache bag longer than TT bag): 2-deep ----
    for (; j + 4 <= jlast; j += 8) {
        const int ya = __ldg(cached_indices + j);
        const int yb = __ldg(cached_indices + j + 4);
        const float4 fa = __ldcg((const float4*)(cache_table + (size_t)ya * EMBD) + lane);
        const float4 fb = __ldcg((const float4*)(cache_table + (size_t)yb * EMBD) + lane);
        cv.x += fa.x + fb.x; cv.y += fa.y + fb.y;
        cv.z += fa.z + fb.z; cv.w += fa.w + fb.w;
    }
    if (j <= jlast) {
        const int ya = __ldg(cached_indices + j);
        const float4 fa = __ldcg((const float4*)(cache_table + (size_t)ya * EMBD) + lane);
        cv.x += fa.x; cv.y += fa.y; cv.z += fa.z; cv.w += fa.w;
    }
    ((float4*)s_cache[w])[lane] = cv;

    // ---- TT reduce across the 8 c-lanes of each q-group ----
    #pragma unroll
    for (int off = 1; off < 8; off <<= 1)
        #pragma unroll
        for (int m = 0; m < 4; ++m)
            #pragma unroll
            for (int z = 0; z < 8; ++z)
                acc[m][z] += __shfl_xor_sync(0xffffffffu, acc[m][z], off);

    float v0, v1, v2, v3;
    switch (c8) {
        case 0: v0=acc[0][0]; v1=acc[1][0]; v2=acc[2][0]; v3=acc[3][0]; break;
        case 1: v0=acc[0][1]; v1=acc[1][1]; v2=acc[2][1]; v3=acc[3][1]; break;
        case 2: v0=acc[0][2]; v1=acc[1][2]; v2=acc[2][2]; v3=acc[3][2]; break;
        case 3: v0=acc[0][3]; v1=acc[1][3]; v2=acc[2][3]; v3=acc[3][3]; break;
        case 4: v0=acc[0][4]; v1=acc[1][4]; v2=acc[2][4]; v3=acc[3][4]; break;
        case 5: v0=acc[0][5]; v1=acc[1][5]; v2=acc[2][5]; v3=acc[3][5]; break;
        case 6: v0=acc[0][6]; v1=acc[1][6]; v2=acc[2][6]; v3=acc[3][6]; break;
        default:v0=acc[0][7]; v1=acc[1][7]; v2=acc[2][7]; v3=acc[3][7]; break;
    }
    const int e0 = q * 32 + c8;          // element = q*32 + m*8 + c8
    s_part[w][e0]      = v0;
    s_part[w][e0 + 8]  = v1;
    s_part[w][e0 + 16] = v2;
    s_part[w][e0 + 24] = v3;
    __syncthreads();

    const float tt = (s_part[0][tid] + s_part[1][tid])
                   + (s_part[2][tid] + s_part[3][tid]);
    const float cc = (s_cache[0][tid] + s_cache[1][tid])
                   + (s_cache[2][tid] + s_cache[3][tid]);

    out[(size_t)b * EMBD + tid] = tt + cc;
}

// ---------------------------------------------------------------------------
extern "C" void kernel_launch(void* const* d_in, const int* in_sizes, int n_in,
                              void* d_out, int out_size)
{
    const int*   indices        = (const int*)d_in[0];
    const int*   offsets        = (const int*)d_in[1];
    const int*   cached_indices = (const int*)d_in[2];
    const int*   cached_offsets = (const int*)d_in[3];
    const float* core0          = (const float*)d_in[4];
    const float* core1          = (const float*)d_in[5];
    const float* core2          = (const float*)d_in[6];
    const float* cache_table    = (const float*)d_in[7];
    float* out = (float*)d_out;

    const int num_bags = out_size / EMBD;   // 4096
    const int n_cached = in_sizes[2];       // 204800

    tt_stage1<<<NPAIR + NROW2, 128>>>(core0, core1, core2);
    bag_kernel<<<num_bags, 128>>>(indices, offsets, cached_indices,
                                  cached_offsets, cache_table, out,
                                  num_bags, n_cached);
}

// round 15
// speedup vs baseline: 1.0843x; 1.0843x over previous
#include <cuda_runtime.h>
#include <cstdint>

// Problem constants (from reference)
#define NROW0 50
#define NROW1 50
#define NROW2 50
#define NPAIR (NROW0 * NROW1)       // 2500 (d0,d1) combos
#define TROW  512                   // t row = 16 (k) x 32 (r2) floats
#define G1LEN 4096                  // core1 row: 32*4*32
#define G0LEN 128                   // core0 row: 1*4*32
#define G2LEN 256                   // core2 row: 32*8
#define EMBD  128

#define S1_GRP 10                   // d0-groups per d1 (5 d0 each)
#define S1_D0  5
#define S1_TT_BLOCKS (NROW1 * S1_GRP)   // 500

// Scratch (global, allocation-free)
__device__ __align__(16) float g_t_table[NPAIR * TROW];   // [p][k*32+r], 5.12 MB (L2)
__device__ __align__(16) float g_core2t[NROW2 * G2LEN];   // [d2][z*32+r], 51.2 KB (L1)

__device__ __forceinline__ void prefetch_l1(const void* p) {
    asm volatile("prefetch.global.L1 [%0];" :: "l"(p));
}

// ---------------------------------------------------------------------------
// Stage 1 (fused): blocks 0..499 build t_table (5 p's per block, one core1-row
// smem fill amortized over 5 d0's); blocks 500..549 transpose core2.
// ---------------------------------------------------------------------------
__global__ void __launch_bounds__(128) tt_stage1(const float* __restrict__ core0,
                                                 const float* __restrict__ core1,
                                                 const float* __restrict__ core2)
{
    const int tid = threadIdx.x;

    if (blockIdx.x >= S1_TT_BLOCKS) {
        const int base = (blockIdx.x - S1_TT_BLOCKS) * G2LEN;
        #pragma unroll
        for (int h = 0; h < 2; ++h) {
            const int u   = base + h * 128 + tid;
            const int d2  = u >> 8;
            const int rem = u & 255;
            const int r   = rem >> 3;
            const int z   = rem & 7;
            g_core2t[(d2 << 8) + (z << 5) + r] = core2[u];
        }
        return;
    }

    __shared__ __align__(16) float s_g1[G1LEN];
    __shared__ __align__(16) float s_g0[S1_D0 * G0LEN];   // 640 floats

    const int b  = blockIdx.x;
    const int d1 = b % NROW1;
    const int g  = b / NROW1;            // 0..9
    const int d0base = g * S1_D0;

    const float4* __restrict__ g1v = (const float4*)(core1 + (size_t)d1 * G1LEN);
    float4* s1v = (float4*)s_g1;
    #pragma unroll
    for (int t = 0; t < G1LEN / 4 / 128; ++t)
        s1v[t * 128 + tid] = __ldg(g1v + t * 128 + tid);
    {
        const float4* __restrict__ g0v =
            (const float4*)(core0 + (size_t)d0base * G0LEN);
        float4* s0v = (float4*)s_g0;
        for (int u = tid; u < S1_D0 * G0LEN / 4; u += 128)
            s0v[u] = __ldg(g0v + u);
    }
    __syncthreads();

    #pragma unroll
    for (int dd = 0; dd < S1_D0; ++dd) {
        const float* g0r = s_g0 + dd * G0LEN;
        float a0 = 0.f, a1 = 0.f, a2 = 0.f, a3 = 0.f;
        #pragma unroll
        for (int r = 0; r < 32; ++r) {
            const float v = s_g1[r * 128 + tid];
            a0 = fmaf(g0r[r],      v, a0);
            a1 = fmaf(g0r[32 + r], v, a1);
            a2 = fmaf(g0r[64 + r], v, a2);
            a3 = fmaf(g0r[96 + r], v, a3);
        }
        const int p = (d0base + dd) * NROW1 + d1;
        float* o = g_t_table + (size_t)p * TROW;
        o[tid]       = a0;
        o[tid + 128] = a1;
        o[tid + 256] = a2;
        o[tid + 384] = a3;
    }
}

// ---------------------------------------------------------------------------
// Stage 2: one bag per block; each TT index handled by ONE warp (4-way split).
// Lane (q=lane>>3, c8=lane&7): 4x8 scalar register tile acc[m][z].
// Pipeline: idx 2 iterations ahead; next t row via prefetch.global.L1
// (no destination registers -> no double-buffer, no rotation MOVs); current
// t row loaded at loop top as L1 hits.  6 blocks/SM.
// Cache bag: per-warp rows, MLP 8, first-round y preloaded before reduction.
// ---------------------------------------------------------------------------
__global__ void __launch_bounds__(128, 6) bag_kernel(
    const int*   __restrict__ indices,
    const int*   __restrict__ offsets,
    const int*   __restrict__ cached_indices,
    const int*   __restrict__ cached_offsets,
    const float* __restrict__ cache_table,
    float*       __restrict__ out,
    int num_bags)
{
    __shared__ float s_part[4][EMBD];
    __shared__ __align__(16) float s_cache[4][EMBD];
    const int tid  = threadIdx.x;
    const int w    = tid >> 5;
    const int lane = tid & 31;
    const int q    = lane >> 3;
    const int c8   = lane & 7;
    const int b    = blockIdx.x;

    const int i0 = __ldg(offsets + b);
    const int i1 = __ldg(offsets + b + 1);
    const int j0 = __ldg(cached_offsets + b);
    const int j1 = __ldg(cached_offsets + b + 1);

    float acc[4][8];
    #pragma unroll
    for (int m = 0; m < 4; ++m)
        #pragma unroll
        for (int z = 0; z < 8; ++z) acc[m][z] = 0.f;

    // ---- TT bag: warp w takes indices i0+w, i0+w+4, ... ----
    {
        const float4* __restrict__ tbase = (const float4*)g_t_table;
        const int toff = q * 32 + c8;
        const int ilast = i1 - 1;

        int i = i0 + w;
        int d2_c = 0;
        int idx_n = 0;
        const float4* tr = tbase;

        if (i < i1) {
            const int idx = __ldg(indices + i);
            const int pq  = idx / 50;
            d2_c = idx - pq * 50;
            tr = tbase + pq * 128 + toff;
            prefetch_l1(tr);
            prefetch_l1(tr + 8);
            prefetch_l1(tr + 16);
            prefetch_l1(tr + 24);
            const int in4 = (i + 4 <= ilast) ? (i + 4) : i;
            idx_n = __ldg(indices + in4);
        }

        for (; i < i1; i += 4) {
            // Current t row (L1 hits thanks to last iteration's prefetch).
            const float4 t0 = __ldg(tr);
            const float4 t1 = __ldg(tr + 8);
            const float4 t2 = __ldg(tr + 16);
            const float4 t3 = __ldg(tr + 24);

            // Stage 0: idx for i+8.
            const int in8 = (i + 8 <= ilast) ? (i + 8) : i;
            const int idx_nn = __ldg(indices + in8);

            // Stage 1: idx_n -> div -> prefetch next t row (registerless).
            const int pq_n = idx_n / 50;
            const int d2_n = idx_n - pq_n * 50;
            const float4* trn = tbase + pq_n * 128 + toff;
            prefetch_l1(trn);
            prefetch_l1(trn + 8);
            prefetch_l1(trn + 16);
            prefetch_l1(trn + 24);

            // Stage 2: FMA block for current index i.
            const float4* __restrict__ cr =
                (const float4*)g_core2t + (d2_c << 6) + c8;

            #define FMA_Z(CZ, Z)                                       \
                acc[0][Z] = fmaf(t0.x, CZ.x, acc[0][Z]);               \
                acc[0][Z] = fmaf(t0.y, CZ.y, acc[0][Z]);               \
                acc[0][Z] = fmaf(t0.z, CZ.z, acc[0][Z]);               \
                acc[0][Z] = fmaf(t0.w, CZ.w, acc[0][Z]);               \
                acc[1][Z] = fmaf(t1.x, CZ.x, acc[1][Z]);               \
                acc[1][Z] = fmaf(t1.y, CZ.y, acc[1][Z]);               \
                acc[1][Z] = fmaf(t1.z, CZ.z, acc[1][Z]);               \
                acc[1][Z] = fmaf(t1.w, CZ.w, acc[1][Z]);               \
                acc[2][Z] = fmaf(t2.x, CZ.x, acc[2][Z]);               \
                acc[2][Z] = fmaf(t2.y, CZ.y, acc[2][Z]);               \
                acc[2][Z] = fmaf(t2.z, CZ.z, acc[2][Z]);               \
                acc[2][Z] = fmaf(t2.w, CZ.w, acc[2][Z]);               \
                acc[3][Z] = fmaf(t3.x, CZ.x, acc[3][Z]);               \
                acc[3][Z] = fmaf(t3.y, CZ.y, acc[3][Z]);               \
                acc[3][Z] = fmaf(t3.z, CZ.z, acc[3][Z]);               \
                acc[3][Z] = fmaf(t3.w, CZ.w, acc[3][Z]);

            {
                float4 c0 = __ldg(cr);
                float4 c1 = __ldg(cr + 8);
                float4 c2 = __ldg(cr + 16);
                float4 c3 = __ldg(cr + 24);
                FMA_Z(c0, 0) FMA_Z(c1, 1) FMA_Z(c2, 2) FMA_Z(c3, 3)
            }
            {
                float4 c4 = __ldg(cr + 32);
                float4 c5 = __ldg(cr + 40);
                float4 c6 = __ldg(cr + 48);
                float4 c7 = __ldg(cr + 56);
                FMA_Z(c4, 4) FMA_Z(c5, 5) FMA_Z(c6, 6) FMA_Z(c7, 7)
            }
            #undef FMA_Z

            // Rotate (pointers/scalars only — no vector MOVs).
            tr = trn;
            d2_c = d2_n;
            idx_n = idx_nn;
        }
    }

    // ---- preload first round of cache y-indices (overlaps reduction) ----
    int y[8];
    int j = j0 + w;
    const int jlast = j1 - 1;
    #pragma unroll
    for (int u = 0; u < 8; ++u) {
        const int jj = (j + u * 4 <= jlast) ? (j + u * 4) : j0;
        y[u] = (j <= jlast) ? __ldg(cached_indices + jj) : 0;
    }

    // ---- TT reduce across the 8 c-lanes of each q-group ----
    #pragma unroll
    for (int off = 1; off < 8; off <<= 1)
        #pragma unroll
        for (int m = 0; m < 4; ++m)
            #pragma unroll
            for (int z = 0; z < 8; ++z)
                acc[m][z] += __shfl_xor_sync(0xffffffffu, acc[m][z], off);

    float v0, v1, v2, v3;
    switch (c8) {
        case 0: v0=acc[0][0]; v1=acc[1][0]; v2=acc[2][0]; v3=acc[3][0]; break;
        case 1: v0=acc[0][1]; v1=acc[1][1]; v2=acc[2][1]; v3=acc[3][1]; break;
        case 2: v0=acc[0][2]; v1=acc[1][2]; v2=acc[2][2]; v3=acc[3][2]; break;
        case 3: v0=acc[0][3]; v1=acc[1][3]; v2=acc[2][3]; v3=acc[3][3]; break;
        case 4: v0=acc[0][4]; v1=acc[1][4]; v2=acc[2][4]; v3=acc[3][4]; break;
        case 5: v0=acc[0][5]; v1=acc[1][5]; v2=acc[2][5]; v3=acc[3][5]; break;
        case 6: v0=acc[0][6]; v1=acc[1][6]; v2=acc[2][6]; v3=acc[3][6]; break;
        default:v0=acc[0][7]; v1=acc[1][7]; v2=acc[2][7]; v3=acc[3][7]; break;
    }
    const int e0 = q * 32 + c8;          // element = q*32 + m*8 + c8
    s_part[w][e0]      = v0;
    s_part[w][e0 + 8]  = v1;
    s_part[w][e0 + 16] = v2;
    s_part[w][e0 + 24] = v3;

    // ---- cached-table bag: per-warp rows, MLP 8, float4 slice per lane ----
    {
        float4 cv = make_float4(0.f, 0.f, 0.f, 0.f);
        if (j <= jlast) {
            #pragma unroll
            for (int u = 0; u < 8; ++u) {
                if (j + u * 4 <= jlast) {
                    const float4 f = __ldcg(
                        (const float4*)(cache_table + (size_t)y[u] * EMBD) + lane);
                    cv.x += f.x; cv.y += f.y; cv.z += f.z; cv.w += f.w;
                }
            }
            j += 32;
        }
        for (; j + 28 <= jlast; j += 32) {
            int yy[8];
            #pragma unroll
            for (int u = 0; u < 8; ++u)
                yy[u] = __ldg(cached_indices + j + u * 4);
            #pragma unroll
            for (int u = 0; u < 8; ++u) {
                const float4 f = __ldcg(
                    (const float4*)(cache_table + (size_t)yy[u] * EMBD) + lane);
                cv.x += f.x; cv.y += f.y; cv.z += f.z; cv.w += f.w;
            }
        }
        for (; j <= jlast; j += 4) {
            const int yv = __ldg(cached_indices + j);
            const float4 f = __ldcg(
                (const float4*)(cache_table + (size_t)yv * EMBD) + lane);
            cv.x += f.x; cv.y += f.y; cv.z += f.z; cv.w += f.w;
        }
        ((float4*)s_cache[w])[lane] = cv;
    }
    __syncthreads();

    const float tt = (s_part[0][tid] + s_part[1][tid])
                   + (s_part[2][tid] + s_part[3][tid]);
    const float cc = (s_cache[0][tid] + s_cache[1][tid])
                   + (s_cache[2][tid] + s_cache[3][tid]);

    out[(size_t)b * EMBD + tid] = tt + cc;
}

// ---------------------------------------------------------------------------
extern "C" void kernel_launch(void* const* d_in, const int* in_sizes, int n_in,
                              void* d_out, int out_size)
{
    const int*   indices        = (const int*)d_in[0];
    const int*   offsets        = (const int*)d_in[1];
    const int*   cached_indices = (const int*)d_in[2];
    const int*   cached_offsets = (const int*)d_in[3];
    const float* core0          = (const float*)d_in[4];
    const float* core1          = (const float*)d_in[5];
    const float* core2          = (const float*)d_in[6];
    const float* cache_table    = (const float*)d_in[7];
    float* out = (float*)d_out;

    const int num_bags = out_size / EMBD;   // 4096

    tt_stage1<<<S1_TT_BLOCKS + NROW2, 128>>>(core0, core1, core2);
    bag_kernel<<<num_bags, 128>>>(indices, offsets, cached_indices,
                                  cached_offsets, cache_table, out, num_bags);
}